// round 2
// baseline (speedup 1.0000x reference)
#include <cuda_runtime.h>
#include <cuda_bf16.h>
#include <cstdint>

#define NNODES 100000
#define HD 128
#define ROW 640   // 5*HD

// scratch layout (floats):
// [0,1e5)       cnt_src
// [1e5,2e5)     cnt_dst
// [2e5,3e5)     sum(type*event_mask)  by src
// [3e5,4e5)     sum(type*dst_mask)    by dst
// [4e5,5e5)     sum(src_mask*event_mask) by src
// [5e5,6e5)     sum(dst_mask*dst_mask)   by dst
// [6e5,7e5)     inv_cnt_src
// [7e5,8e5)     inv_cnt_dst
__device__ float g_scratch[800000];

// ---------------------------------------------------------------------------
// accurate-enough fast cos: Cody-Waite (FMA) reduction + cephes minimax polys.
// |x| <= ~1000 in this workload; abs err ~1e-7.
// ---------------------------------------------------------------------------
__device__ __forceinline__ float fast_cos(float x) {
    float j = rintf(x * 0.63661977236758134f);    // x * 2/pi
    int   q = (int)j;
    // r = x - j*pi/2, two-step with exact FMA products
    float r = fmaf(j, -1.5707963705062866f, x);   // float(pi/2) = pi/2 + 4.37e-8
    r = fmaf(j, 4.3711390e-8f, r);                // put the excess back
    float r2 = r * r;
    // sin poly on [-pi/4, pi/4]
    float ps = fmaf(r2, -1.9515295891e-4f, 8.3321608736e-3f);
    ps = fmaf(r2, ps, -1.6666654611e-1f);
    float s  = fmaf(r * r2, ps, r);
    // cos poly on [-pi/4, pi/4]
    float pc = fmaf(r2, 2.443315711809948e-5f, -1.388731625493765e-3f);
    pc = fmaf(r2, pc, 4.166664568298827e-2f);
    pc = fmaf(r2, pc, -0.5f);
    float c  = fmaf(r2, pc, 1.0f);
    float v = (q & 1) ? s : c;
    if ((q + 1) & 2) v = -v;
    return v;
}

// ---------------------------------------------------------------------------
// Kernel 1: zero the atomic-accumulation region (blocks 2..4 of every row)
// and the scalar scratch. blockDim = 128.
// ---------------------------------------------------------------------------
__global__ void k_zero(float* __restrict__ out) {
    int bid = blockIdx.x, tid = threadIdx.x;
    if (bid < 2 * NNODES) {
        float* p = out + (size_t)bid * ROW + 256;
        p[tid]       = 0.0f;
        p[tid + 128] = 0.0f;
        p[tid + 256] = 0.0f;
    } else {
        int idx = (bid - 2 * NNODES) * 128 + tid;
        if (idx < 600000) g_scratch[idx] = 0.0f;
    }
}

// ---------------------------------------------------------------------------
// Kernel 2: per-event scalar accumulations (counts + factored block sums).
// ---------------------------------------------------------------------------
__global__ void k_count(const int* __restrict__ type, const int* __restrict__ src,
                        const float* __restrict__ sm, const int* __restrict__ dst,
                        const float* __restrict__ dm, const float* __restrict__ em,
                        int L) {
    int i = blockIdx.x * blockDim.x + threadIdx.x;
    if (i >= L) return;
    int s = src[i], d = dst[i];
    float e = em[i], dmv = dm[i], smv = sm[i];
    float ty = (float)type[i];
    atomicAdd(&g_scratch[s],               1.0f);
    atomicAdd(&g_scratch[100000 + d],      1.0f);
    atomicAdd(&g_scratch[200000 + s],      ty * e);
    atomicAdd(&g_scratch[300000 + d],      ty * dmv);
    atomicAdd(&g_scratch[400000 + s],      smv * e);
    atomicAdd(&g_scratch[500000 + d],      dmv * dmv);
}

// ---------------------------------------------------------------------------
// Kernel 3: per-node — store inverse counts for the scatter kernel, and write
// the two factored blocks (0: type scalar, 1: memory[n]*scalar) directly.
// blockDim = 128, one block per node.
// ---------------------------------------------------------------------------
__global__ void k_nodeinit(const float* __restrict__ mem, float* __restrict__ out) {
    int n = blockIdx.x, h = threadIdx.x;
    float inv_s = 1.0f / fmaxf(g_scratch[n],          1.0f);
    float inv_d = 1.0f / fmaxf(g_scratch[100000 + n], 1.0f);
    if (h == 0) {
        g_scratch[600000 + n] = inv_s;
        g_scratch[700000 + n] = inv_d;
    }
    float a0s = g_scratch[200000 + n] * inv_s;
    float a0d = g_scratch[300000 + n] * inv_d;
    float c1s = g_scratch[400000 + n] * inv_s;
    float c1d = g_scratch[500000 + n] * inv_d;
    float mv  = mem[(size_t)n * HD + h];
    float* os = out + (size_t)n * ROW;
    float* od = out + (size_t)(NNODES + n) * ROW;
    os[h]       = a0s;
    os[128 + h] = mv * c1s;
    od[h]       = a0d;
    od[128 + h] = mv * c1d;
}

// ---------------------------------------------------------------------------
// Kernel 4: per-event vector scatter of blocks 2..4, pre-scaled by inverse
// counts. One warp per event; lane l handles h = l + 32k so each atomicAdd
// instruction is one fully-coalesced 128B line.
// ---------------------------------------------------------------------------
__global__ void k_scatter(const int* __restrict__ src, const float* __restrict__ sm,
                          const int* __restrict__ dst, const float* __restrict__ dm,
                          const float* __restrict__ E, const float* __restrict__ em,
                          const float* __restrict__ ts, const float* __restrict__ mem,
                          const float* __restrict__ lu, const float* __restrict__ w,
                          const float* __restrict__ b, float* __restrict__ out,
                          int L) {
    int warp = (blockIdx.x * blockDim.x + threadIdx.x) >> 5;
    int lane = threadIdx.x & 31;
    if (warp >= L) return;
    int i = warp;

    int   s   = src[i], d = dst[i];
    float smv = sm[i],  dmv = dm[i], emv = em[i], t = ts[i];
    float inv_s = g_scratch[600000 + s];
    float inv_d = g_scratch[700000 + d];
    float lus = lu[s], lud = lu[d];

    // NOTE: reference multiplies BOTH last_updates by dst_mask (faithful bug)
    float xs = t - lus * dmv;
    float xd = t - lud * dmv;

    float ce  = emv * inv_s;   // src-side message scale (event_mask), pre-divided
    float cd  = dmv * inv_d;   // dst-side message scale (dst_mask), pre-divided
    float ced = dmv * ce;      // memory[dst]*dst_mask*event_mask / cnt_src
    float cds = smv * cd;      // memory[src]*src_mask*dst_mask   / cnt_dst

    const float* mrow_s = mem + (size_t)s * HD;
    const float* mrow_d = mem + (size_t)d * HD;
    const float* erow   = E   + (size_t)i * HD;
    float* out_s = out + (size_t)s * ROW;
    float* out_d = out + (size_t)(NNODES + d) * ROW;

#pragma unroll
    for (int k = 0; k < 4; k++) {
        int h = lane + 32 * k;
        float wv = __ldg(w + h), bv = __ldg(b + h);
        float ms = mrow_s[h], md = mrow_d[h], ev = erow[h];
        atomicAdd(out_s + 256 + h, md * ced);
        atomicAdd(out_s + 384 + h, fast_cos(fmaf(xs, wv, bv)) * ce);
        atomicAdd(out_s + 512 + h, ev * ce);
        atomicAdd(out_d + 256 + h, ms * cds);
        atomicAdd(out_d + 384 + h, fast_cos(fmaf(xd, wv, bv)) * cd);
        atomicAdd(out_d + 512 + h, ev * cd);
    }
}

// ---------------------------------------------------------------------------
extern "C" void kernel_launch(void* const* d_in, const int* in_sizes, int n_in,
                              void* d_out, int out_size) {
    const int*   type = (const int*)  d_in[0];
    const int*   src  = (const int*)  d_in[1];
    const float* smk  = (const float*)d_in[2];
    const int*   dst  = (const int*)  d_in[3];
    const float* dmk  = (const float*)d_in[4];
    const float* E    = (const float*)d_in[5];
    const float* em   = (const float*)d_in[6];
    const float* ts   = (const float*)d_in[7];
    const float* mem  = (const float*)d_in[8];
    const float* lu   = (const float*)d_in[9];
    const float* w    = (const float*)d_in[10];
    const float* b    = (const float*)d_in[11];
    float* out = (float*)d_out;
    int L = in_sizes[0];

    // 1) zero atomic region + scratch: 2N row-blocks + ceil(600000/128) blocks
    int zgrid = 2 * NNODES + (600000 + 127) / 128;
    k_zero<<<zgrid, 128>>>(out);
    // 2) per-event scalar sums
    k_count<<<(L + 255) / 256, 256>>>(type, src, smk, dst, dmk, em, L);
    // 3) per-node: inverse counts + factored blocks 0,1
    k_nodeinit<<<NNODES, 128>>>(mem, out);
    // 4) per-event vector scatter of blocks 2..4 (one warp per event)
    k_scatter<<<(L + 7) / 8, 256>>>(src, smk, dst, dmk, E, em, ts, mem, lu, w, b,
                                    out, L);
}